// round 16
// baseline (speedup 1.0000x reference)
#include <cuda_runtime.h>

#define IN_SIZE 448
#define OUT_SIZE 224
#define BATCH 64
#define NTHREADS 224
#define ROWS_PER_BLK 2

// fast sigmoid(10z): MUFU-based; saturates exactly to 0/1 for large |10z|.
__device__ __forceinline__ float sig10f(float z) {
    return 1.0f / (1.0f + __expf(-10.0f * z));
}

// ---------------------------------------------------------------------------
// Champion config at finer granularity: RPB=2 (grid 112x64) to shrink the
// wave-tail quantum; saturation fast path keeps the per-block prologue cheap.
// ---------------------------------------------------------------------------
__global__ void __launch_bounds__(NTHREADS) racnn_fused(
    const float* __restrict__ images,
    const float* __restrict__ locs,
    float* __restrict__ out)
{
    __shared__ float4 s_rowe[ROWS_PER_BLK];  // {r0off(int bits), r1off(int bits), a0, a1}

    const int jr0 = blockIdx.x * ROWS_PER_BLK;
    const int b   = blockIdx.y;
    const int jc  = threadIdx.x;

    // ---- per-batch crop params (broadcast) ----
    float tx = locs[b * 3 + 0];
    float ty = locs[b * 3 + 1];
    float tl = locs[b * 3 + 2];

    tl = fmaxf(tl, 448.0f / 3.0f);
    tx = fminf(fmaxf(tx, tl), (float)IN_SIZE - tl);
    ty = fminf(fmaxf(ty, tl), (float)IN_SIZE - tl);

    const float w_off = fmaxf(floorf(tx - tl), 0.0f);
    const float h_off = fmaxf(floorf(ty - tl), 0.0f);
    const float w_end = fminf(floorf(tx + tl), (float)IN_SIZE);
    const float h_end = fminf(floorf(ty + tl), (float)IN_SIZE);

    // ---- row entries: threads 0..1 ----
    if (jc < ROWS_PER_BLK) {
        const float jf = (float)(jr0 + jc);
        const float src_r = w_off + (jf * (w_end - w_off - 1.0f)) / (float)(OUT_SIZE - 1);
        float r0 = fminf(fmaxf(floorf(src_r), 0.0f), (float)(IN_SIZE - 1));
        const float wr = src_r - r0;
        const int r0i = (int)r0;
        const int r1i = min(r0i + 1, IN_SIZE - 1);
        const float mrow0 = sig10f((float)r0i - w_off) - sig10f((float)r0i - w_end);
        const float mrow1 = sig10f((float)r1i - w_off) - sig10f((float)r1i - w_end);
        float4 e;
        e.x = __int_as_float(r0i * IN_SIZE);
        e.y = __int_as_float(r1i * IN_SIZE);
        e.z = (1.0f - wr) * mrow0;
        e.w = wr * mrow1;
        s_rowe[jc] = e;
    }

    // ---- col entry: per thread; saturation fast path for middle warps ----
    // Col stride >= 297/223 = 1.332 -> for 32<=jc<192 the mask args exceed
    // ~41 in magnitude with the right signs -> mcol == 1 exactly in fp32.
    const float jf = (float)jc;
    const float src_c = h_off + (jf * (h_end - h_off - 1.0f)) / (float)(OUT_SIZE - 1);
    float c0 = fminf(fmaxf(floorf(src_c), 0.0f), (float)(IN_SIZE - 1));
    const float wc = src_c - c0;
    const int c0i = (int)c0;
    const int c1i = min(c0i + 1, IN_SIZE - 1);

    float mcol0 = 1.0f, mcol1 = 1.0f;
    if (jc < 32 || jc >= 192) {   // warp-uniform (warps 0 and 6 only)
        mcol0 = sig10f((float)c0i - h_off) - sig10f((float)c0i - h_end);
        mcol1 = sig10f((float)c1i - h_off) - sig10f((float)c1i - h_end);
    }
    const float b0 = (1.0f - wc) * mcol0;
    const float b1 = wc * mcol1;

    __syncthreads();

    const int img_base = b * 3 * IN_SIZE * IN_SIZE;
    const int out_base = b * 3 * OUT_SIZE * OUT_SIZE + jr0 * OUT_SIZE + jc;

    // ---- gather: one row per iteration, 12-load batches ----
#pragma unroll
    for (int r = 0; r < ROWS_PER_BLK; r++) {
        const float4 re = s_rowe[r];
        const int   p0 = img_base + __float_as_int(re.x);
        const int   p1 = img_base + __float_as_int(re.y);
        const float a0 = re.z;
        const float a1 = re.w;

        float x00[3], x01[3], x10[3], x11[3];
#pragma unroll
        for (int ch = 0; ch < 3; ch++) {
            const int cofs = ch * (IN_SIZE * IN_SIZE);
            x00[ch] = __ldg(images + p0 + cofs + c0i);
            x01[ch] = __ldg(images + p0 + cofs + c1i);
            x10[ch] = __ldg(images + p1 + cofs + c0i);
            x11[ch] = __ldg(images + p1 + cofs + c1i);
        }
#pragma unroll
        for (int ch = 0; ch < 3; ch++) {
            const float top = fmaf(b1, x01[ch], b0 * x00[ch]);
            const float bot = fmaf(b1, x11[ch], b0 * x10[ch]);
            const float v = fmaf(a1, bot, a0 * top);
            __stcs(out + out_base + ch * (OUT_SIZE * OUT_SIZE) + r * OUT_SIZE, v);
        }
    }
}

extern "C" void kernel_launch(void* const* d_in, const int* in_sizes, int n_in,
                              void* d_out, int out_size) {
    const float* images = (const float*)d_in[0];
    const float* locs   = (const float*)d_in[1];
    float* out = (float*)d_out;

    dim3 grid(OUT_SIZE / ROWS_PER_BLK, BATCH);
    racnn_fused<<<grid, NTHREADS>>>(images, locs, out);
}

// round 17
// speedup vs baseline: 1.2168x; 1.2168x over previous
#include <cuda_runtime.h>

#define IN_SIZE 448
#define OUT_SIZE 224
#define BATCH 64
#define NTHREADS 224
#define ROWS_PER_BLK 4

// fast sigmoid(10z): MUFU-based; saturates exactly to 0/1 for large |10z|.
__device__ __forceinline__ float sig10f(float z) {
    return 1.0f / (1.0f + __expf(-10.0f * z));
}

// ---------------------------------------------------------------------------
// R14 champion (RPB4 + col-mask saturation fast path + __stcs) plus the same
// saturation fast path applied to the ROW masks: for 32 <= jr < 192 the row
// mask is exactly 1 in fp32 (min stride 1.332 -> |arg*10| >= ~410), and the
// test is block-uniform, so 40/56 rowgroups skip all row-mask MUFUs in the
// pre-barrier critical path.  grid=(56, 64), block=224.
// ---------------------------------------------------------------------------
__global__ void __launch_bounds__(NTHREADS) racnn_fused(
    const float* __restrict__ images,
    const float* __restrict__ locs,
    float* __restrict__ out)
{
    __shared__ float4 s_rowe[ROWS_PER_BLK];  // {r0off(int bits), r1off(int bits), a0, a1}

    const int jr0 = blockIdx.x * ROWS_PER_BLK;
    const int b   = blockIdx.y;
    const int jc  = threadIdx.x;

    // ---- per-batch crop params (broadcast) ----
    float tx = locs[b * 3 + 0];
    float ty = locs[b * 3 + 1];
    float tl = locs[b * 3 + 2];

    tl = fmaxf(tl, 448.0f / 3.0f);
    tx = fminf(fmaxf(tx, tl), (float)IN_SIZE - tl);
    ty = fminf(fmaxf(ty, tl), (float)IN_SIZE - tl);

    const float w_off = fmaxf(floorf(tx - tl), 0.0f);
    const float h_off = fmaxf(floorf(ty - tl), 0.0f);
    const float w_end = fminf(floorf(tx + tl), (float)IN_SIZE);
    const float h_end = fminf(floorf(ty + tl), (float)IN_SIZE);

    // ---- row entries: threads 0..3; saturation fast path for middle blocks ----
    if (jc < ROWS_PER_BLK) {
        const int jr = jr0 + jc;
        const float jf = (float)jr;
        const float src_r = w_off + (jf * (w_end - w_off - 1.0f)) / (float)(OUT_SIZE - 1);
        float r0 = fminf(fmaxf(floorf(src_r), 0.0f), (float)(IN_SIZE - 1));
        const float wr = src_r - r0;
        const int r0i = (int)r0;
        const int r1i = min(r0i + 1, IN_SIZE - 1);

        float mrow0 = 1.0f, mrow1 = 1.0f;
        if (jr0 < 32 || jr0 + ROWS_PER_BLK > 192) {   // block-uniform branch
            mrow0 = sig10f((float)r0i - w_off) - sig10f((float)r0i - w_end);
            mrow1 = sig10f((float)r1i - w_off) - sig10f((float)r1i - w_end);
        }

        float4 e;
        e.x = __int_as_float(r0i * IN_SIZE);
        e.y = __int_as_float(r1i * IN_SIZE);
        e.z = (1.0f - wr) * mrow0;
        e.w = wr * mrow1;
        s_rowe[jc] = e;
    }

    // ---- col entry: per thread; saturation fast path for middle warps ----
    const float jf = (float)jc;
    const float src_c = h_off + (jf * (h_end - h_off - 1.0f)) / (float)(OUT_SIZE - 1);
    float c0 = fminf(fmaxf(floorf(src_c), 0.0f), (float)(IN_SIZE - 1));
    const float wc = src_c - c0;
    const int c0i = (int)c0;
    const int c1i = min(c0i + 1, IN_SIZE - 1);

    float mcol0 = 1.0f, mcol1 = 1.0f;
    if (jc < 32 || jc >= 192) {   // warp-uniform (warps 0 and 6 only)
        mcol0 = sig10f((float)c0i - h_off) - sig10f((float)c0i - h_end);
        mcol1 = sig10f((float)c1i - h_off) - sig10f((float)c1i - h_end);
    }
    const float b0 = (1.0f - wc) * mcol0;
    const float b1 = wc * mcol1;

    __syncthreads();

    const int img_base = b * 3 * IN_SIZE * IN_SIZE;
    const int out_base = b * 3 * OUT_SIZE * OUT_SIZE + jr0 * OUT_SIZE + jc;

    // ---- gather: one row per iteration, 12-load batches ----
#pragma unroll
    for (int r = 0; r < ROWS_PER_BLK; r++) {
        const float4 re = s_rowe[r];
        const int   p0 = img_base + __float_as_int(re.x);
        const int   p1 = img_base + __float_as_int(re.y);
        const float a0 = re.z;
        const float a1 = re.w;

        float x00[3], x01[3], x10[3], x11[3];
#pragma unroll
        for (int ch = 0; ch < 3; ch++) {
            const int cofs = ch * (IN_SIZE * IN_SIZE);
            x00[ch] = __ldg(images + p0 + cofs + c0i);
            x01[ch] = __ldg(images + p0 + cofs + c1i);
            x10[ch] = __ldg(images + p1 + cofs + c0i);
            x11[ch] = __ldg(images + p1 + cofs + c1i);
        }
#pragma unroll
        for (int ch = 0; ch < 3; ch++) {
            const float top = fmaf(b1, x01[ch], b0 * x00[ch]);
            const float bot = fmaf(b1, x11[ch], b0 * x10[ch]);
            const float v = fmaf(a1, bot, a0 * top);
            __stcs(out + out_base + ch * (OUT_SIZE * OUT_SIZE) + r * OUT_SIZE, v);
        }
    }
}

extern "C" void kernel_launch(void* const* d_in, const int* in_sizes, int n_in,
                              void* d_out, int out_size) {
    const float* images = (const float*)d_in[0];
    const float* locs   = (const float*)d_in[1];
    float* out = (float*)d_out;

    dim3 grid(OUT_SIZE / ROWS_PER_BLK, BATCH);
    racnn_fused<<<grid, NTHREADS>>>(images, locs, out);
}